// round 2
// baseline (speedup 1.0000x reference)
#include <cuda_runtime.h>
#include <cuda_fp16.h>
#include <cstdint>

// ============================================================================
// BinaryDense: out[8192,2048] = X[8192,2048] @ (W >= 0 ? 1 : 0)[2048,2048]
// Toolchain targets plain sm_100 (no 'a' features) -> tcgen05 unavailable.
// Path: fp16 mma.sync (HMMA) GEMM, cp.async 4-stage pipeline, fp32 accum.
// ============================================================================

#define B_DIM 8192
#define K_DIM 2048
#define N_DIM 2048

#define BM 128
#define BN 256
#define BK 32
#define STAGES 4
#define KTILES (K_DIM / BK)          // 64

#define A_STAGE_BYTES (BM * BK * 2)  // 8192
#define B_STAGE_BYTES (BN * BK * 2)  // 16384
#define STAGE_BYTES (A_STAGE_BYTES + B_STAGE_BYTES)  // 24576
#define SMEM_TOTAL (STAGES * STAGE_BYTES)            // 98304

// Scratch: fp16 X and binarized+transposed W (Wb is [N, K], K contiguous)
__device__ __align__(1024) __half g_Xh[(size_t)B_DIM * K_DIM];
__device__ __align__(1024) __half g_Wb[(size_t)N_DIM * K_DIM];

// ---------------------------------------------------------------------------
__device__ __forceinline__ uint32_t smem_u32(const void* p) {
    uint32_t a;
    asm("{ .reg .u64 t; cvta.to.shared.u64 t, %1; cvt.u32.u64 %0, t; }"
        : "=r"(a) : "l"(p));
    return a;
}

__device__ __forceinline__ void cp_async16(uint32_t dst, const void* src) {
    asm volatile("cp.async.cg.shared.global [%0], [%1], 16;"
                 :: "r"(dst), "l"(src) : "memory");
}
__device__ __forceinline__ void cp_commit() {
    asm volatile("cp.async.commit_group;" ::: "memory");
}
template <int N>
__device__ __forceinline__ void cp_wait() {
    asm volatile("cp.async.wait_group %0;" :: "n"(N) : "memory");
}

__device__ __forceinline__ void ldsm_x4(uint32_t& r0, uint32_t& r1,
                                        uint32_t& r2, uint32_t& r3, uint32_t a) {
    asm volatile("ldmatrix.sync.aligned.m8n8.x4.shared.b16 {%0,%1,%2,%3}, [%4];"
                 : "=r"(r0), "=r"(r1), "=r"(r2), "=r"(r3) : "r"(a));
}

__device__ __forceinline__ void mma16816(float* d, const uint32_t* a,
                                         const uint32_t* b) {
    asm volatile(
        "mma.sync.aligned.m16n8k16.row.col.f32.f16.f16.f32 "
        "{%0,%1,%2,%3}, {%4,%5,%6,%7}, {%8,%9}, {%0,%1,%2,%3};"
        : "+f"(d[0]), "+f"(d[1]), "+f"(d[2]), "+f"(d[3])
        : "r"(a[0]), "r"(a[1]), "r"(a[2]), "r"(a[3]), "r"(b[0]), "r"(b[1]));
}

// ---------------------------------------------------------------------------
// Kernel 1: X fp32 -> fp16 (8 elems/thread, vectorized)
// ---------------------------------------------------------------------------
__global__ void __launch_bounds__(256) convert_x_kernel(
    const float* __restrict__ x, __half* __restrict__ xh) {
    size_t i = ((size_t)blockIdx.x * blockDim.x + threadIdx.x) * 8;
    float4 v0 = *reinterpret_cast<const float4*>(x + i);
    float4 v1 = *reinterpret_cast<const float4*>(x + i + 4);
    union { __half2 h[4]; uint4 u; } pk;
    pk.h[0] = __floats2half2_rn(v0.x, v0.y);
    pk.h[1] = __floats2half2_rn(v0.z, v0.w);
    pk.h[2] = __floats2half2_rn(v1.x, v1.y);
    pk.h[3] = __floats2half2_rn(v1.z, v1.w);
    *reinterpret_cast<uint4*>(xh + i) = pk.u;
}

// ---------------------------------------------------------------------------
// Kernel 2: binarize W[K,N] and transpose to Wb[N,K] fp16 (tile transpose)
// ---------------------------------------------------------------------------
__global__ void __launch_bounds__(256) binarize_w_kernel(
    const float* __restrict__ w, __half* __restrict__ wb) {
    __shared__ __half tile[32][33];
    int n0 = blockIdx.x * 32, k0 = blockIdx.y * 32;
    int tx = threadIdx.x, ty = threadIdx.y;
#pragma unroll
    for (int r = 0; r < 32; r += 8) {
        float v = w[(size_t)(k0 + ty + r) * N_DIM + n0 + tx];
        tile[ty + r][tx] = __float2half(v < 0.0f ? 0.0f : 1.0f);
    }
    __syncthreads();
#pragma unroll
    for (int r = 0; r < 32; r += 8) {
        wb[(size_t)(n0 + ty + r) * K_DIM + k0 + tx] = tile[tx][ty + r];
    }
}

// ---------------------------------------------------------------------------
// Kernel 3: fp16 HMMA GEMM. 128x256 block tile, BK=32, 4-stage cp.async.
// 256 threads = 8 warps (2 M x 4 N), 64x64 warp tiles, fp32 accumulators.
// Shared-memory rows are 64 B (32 halfs); swizzle: 16B-chunk ^= (row>>1)&3.
// ---------------------------------------------------------------------------
__global__ void __launch_bounds__(256, 1)
bingemm_kernel(const __half* __restrict__ Xh, const __half* __restrict__ Wb,
               float* __restrict__ out) {
    extern __shared__ char smem[];
    const uint32_t sb = smem_u32(smem);

    const int tid = threadIdx.x;
    const int lane = tid & 31;
    const int wid = tid >> 5;
    const int wm = (wid >> 2) * 64;   // warp M offset in tile
    const int wn = (wid & 3) * 64;    // warp N offset in tile

    const int mBase = blockIdx.y * BM;
    const int nBase = blockIdx.x * BN;

    // ---- cp.async source/dest precompute -------------------------------
    // A tile: 128 rows x 4 chunks(16B); B tile: 256 rows x 4 chunks.
    const int aRow0 = tid >> 2;             // rows tid/4 and tid/4+64
    const int aChunk = tid & 3;
    const uint32_t aSw0 = (uint32_t)(aChunk ^ ((aRow0 >> 1) & 3)) * 16;
    const uint32_t aSw1 = (uint32_t)(aChunk ^ (((aRow0 + 64) >> 1) & 3)) * 16;
    const __half* gA0 = Xh + (size_t)(mBase + aRow0) * K_DIM + aChunk * 8;
    const __half* gA1 = gA0 + (size_t)64 * K_DIM;

    const uint32_t bSw0 = aSw0;  // same row pattern for first 128 rows
    const uint32_t bSw1 = aSw1;
    const uint32_t bSw2 = (uint32_t)(aChunk ^ (((aRow0 + 128) >> 1) & 3)) * 16;
    const uint32_t bSw3 = (uint32_t)(aChunk ^ (((aRow0 + 192) >> 1) & 3)) * 16;
    const __half* gB0 = Wb + (size_t)(nBase + aRow0) * K_DIM + aChunk * 8;

    // ---- ldmatrix address precompute (stage-relative) ------------------
    // A frag mi: row = wm + mi*16 + (lane&15), kchunk-bit = lane>>4
    uint32_t aAddr[4];
#pragma unroll
    for (int mi = 0; mi < 4; ++mi) {
        int r = wm + mi * 16 + (lane & 15);
        int kc = lane >> 4;
        aAddr[mi] = (uint32_t)(r * 64 + ((kc ^ ((r >> 1) & 3)) * 16));
    }
    // B frag pair j: row = wn + j*16 + (lane&7) + ((lane>>4)&1)*8,
    //                kchunk-bit = (lane>>3)&1
    uint32_t bAddr[4];
#pragma unroll
    for (int j = 0; j < 4; ++j) {
        int r = wn + j * 16 + (lane & 7) + ((lane >> 4) & 1) * 8;
        int kc = (lane >> 3) & 1;
        bAddr[j] = (uint32_t)(A_STAGE_BYTES + r * 64 + ((kc ^ ((r >> 1) & 3)) * 16));
    }

    float acc[4][8][4];
#pragma unroll
    for (int mi = 0; mi < 4; ++mi)
#pragma unroll
        for (int ni = 0; ni < 8; ++ni)
#pragma unroll
            for (int e = 0; e < 4; ++e) acc[mi][ni][e] = 0.0f;

    // ---- prologue: fill STAGES-1 stages --------------------------------
#pragma unroll
    for (int s = 0; s < STAGES - 1; ++s) {
        uint32_t st = sb + s * STAGE_BYTES;
        int kOff = s * BK;
        cp_async16(st + aRow0 * 64 + aSw0, gA0 + kOff);
        cp_async16(st + (aRow0 + 64) * 64 + aSw1, gA1 + kOff);
        uint32_t bt = st + A_STAGE_BYTES;
        cp_async16(bt + aRow0 * 64 + bSw0, gB0 + kOff);
        cp_async16(bt + (aRow0 + 64) * 64 + bSw1, gB0 + (size_t)64 * K_DIM + kOff);
        cp_async16(bt + (aRow0 + 128) * 64 + bSw2, gB0 + (size_t)128 * K_DIM + kOff);
        cp_async16(bt + (aRow0 + 192) * 64 + bSw3, gB0 + (size_t)192 * K_DIM + kOff);
        cp_commit();
    }

    // ---- mainloop ------------------------------------------------------
    for (int it = 0; it < KTILES; ++it) {
        __syncthreads();  // stage (it+3)%4 fully consumed by iter it-1
        int pf = it + STAGES - 1;
        if (pf < KTILES) {
            uint32_t st = sb + (pf & (STAGES - 1)) * STAGE_BYTES;
            int kOff = pf * BK;
            cp_async16(st + aRow0 * 64 + aSw0, gA0 + kOff);
            cp_async16(st + (aRow0 + 64) * 64 + aSw1, gA1 + kOff);
            uint32_t bt = st + A_STAGE_BYTES;
            cp_async16(bt + aRow0 * 64 + bSw0, gB0 + kOff);
            cp_async16(bt + (aRow0 + 64) * 64 + bSw1, gB0 + (size_t)64 * K_DIM + kOff);
            cp_async16(bt + (aRow0 + 128) * 64 + bSw2, gB0 + (size_t)128 * K_DIM + kOff);
            cp_async16(bt + (aRow0 + 192) * 64 + bSw3, gB0 + (size_t)192 * K_DIM + kOff);
        }
        cp_commit();
        cp_wait<STAGES - 1>();   // stage it complete
        __syncthreads();

        uint32_t stage = sb + (it & (STAGES - 1)) * STAGE_BYTES;
#pragma unroll
        for (int s = 0; s < 2; ++s) {       // two k16 steps per BK=32
            const uint32_t kx = s * 32;     // chunk-bit1 toggle = byte 32 XOR
            uint32_t a[4][4];
#pragma unroll
            for (int mi = 0; mi < 4; ++mi)
                ldsm_x4(a[mi][0], a[mi][1], a[mi][2], a[mi][3],
                        stage + (aAddr[mi] ^ kx));
            uint32_t b[4][4];
#pragma unroll
            for (int j = 0; j < 4; ++j)
                ldsm_x4(b[j][0], b[j][1], b[j][2], b[j][3],
                        stage + (bAddr[j] ^ kx));
#pragma unroll
            for (int mi = 0; mi < 4; ++mi) {
#pragma unroll
                for (int ni = 0; ni < 8; ++ni) {
                    // frag ni: regs (b[ni/2][0..1]) for even, (b[ni/2][2..3]) odd
                    mma16816(acc[mi][ni], a[mi], &b[ni >> 1][(ni & 1) * 2]);
                }
            }
        }
    }

    // ---- epilogue: direct coalesced-sector stores ----------------------
#pragma unroll
    for (int mi = 0; mi < 4; ++mi) {
#pragma unroll
        for (int h = 0; h < 2; ++h) {
            size_t row = (size_t)(mBase + wm + mi * 16 + h * 8 + (lane >> 2));
            float* p = out + row * N_DIM + nBase + wn + (lane & 3) * 2;
#pragma unroll
            for (int ni = 0; ni < 8; ++ni) {
                float2 v = make_float2(acc[mi][ni][2 * h], acc[mi][ni][2 * h + 1]);
                *reinterpret_cast<float2*>(p + ni * 8) = v;
            }
        }
    }
}

// ---------------------------------------------------------------------------
extern "C" void kernel_launch(void* const* d_in, const int* in_sizes, int n_in,
                              void* d_out, int out_size) {
    const float* x = (const float*)d_in[0];   // [8192, 2048] fp32
    const float* w = (const float*)d_in[1];   // [2048, 2048] fp32
    float* out = (float*)d_out;               // [8192, 2048] fp32

    void *xh_ptr = nullptr, *wb_ptr = nullptr;
    cudaGetSymbolAddress(&xh_ptr, g_Xh);
    cudaGetSymbolAddress(&wb_ptr, g_Wb);

    convert_x_kernel<<<(B_DIM * (size_t)K_DIM) / (256 * 8), 256>>>(
        x, (__half*)xh_ptr);
    binarize_w_kernel<<<dim3(N_DIM / 32, K_DIM / 32), dim3(32, 8)>>>(
        w, (__half*)wb_ptr);

    cudaFuncSetAttribute(bingemm_kernel,
                         cudaFuncAttributeMaxDynamicSharedMemorySize, SMEM_TOTAL);
    bingemm_kernel<<<dim3(N_DIM / BN, B_DIM / BM), 256, SMEM_TOTAL>>>(
        (const __half*)xh_ptr, (const __half*)wb_ptr, out);
}

// round 3
// speedup vs baseline: 1.3602x; 1.3602x over previous
#include <cuda_runtime.h>
#include <cuda_fp16.h>
#include <cstdint>

// ============================================================================
// BinaryDense: out[8192,2048] = X[8192,2048] @ (W >= 0 ? 1 : 0)[2048,2048]
// Plain sm_100 target (no tcgen05). fp16 mma.sync HMMA GEMM, fp32 accum.
// R2: 128x128 tile, 2 CTAs/SM, single-sync multistage pipeline.
// ============================================================================

#define B_DIM 8192
#define K_DIM 2048
#define N_DIM 2048

#define BM 128
#define BN 128
#define BK 32
#define STAGES 4
#define KTILES (K_DIM / BK)          // 64

#define A_STAGE_BYTES (BM * BK * 2)  // 8192
#define B_STAGE_BYTES (BN * BK * 2)  // 8192
#define STAGE_BYTES (A_STAGE_BYTES + B_STAGE_BYTES)  // 16384
#define SMEM_TOTAL (STAGES * STAGE_BYTES)            // 65536

#define CONVERT_BLOCKS 8192          // X: 8192*2048 / (256*8)
#define BIN_BLOCKS (64 * 64)         // W 32x32 tiles

// Scratch: fp16 X and binarized+transposed W (Wb is [N, K], K contiguous)
__device__ __align__(1024) __half g_Xh[(size_t)B_DIM * K_DIM];
__device__ __align__(1024) __half g_Wb[(size_t)N_DIM * K_DIM];

// ---------------------------------------------------------------------------
__device__ __forceinline__ uint32_t smem_u32(const void* p) {
    uint32_t a;
    asm("{ .reg .u64 t; cvta.to.shared.u64 t, %1; cvt.u32.u64 %0, t; }"
        : "=r"(a) : "l"(p));
    return a;
}

__device__ __forceinline__ void cp_async16(uint32_t dst, const void* src) {
    asm volatile("cp.async.cg.shared.global [%0], [%1], 16;"
                 :: "r"(dst), "l"(src) : "memory");
}
__device__ __forceinline__ void cp_commit() {
    asm volatile("cp.async.commit_group;" ::: "memory");
}
template <int N>
__device__ __forceinline__ void cp_wait() {
    asm volatile("cp.async.wait_group %0;" :: "n"(N) : "memory");
}

__device__ __forceinline__ void ldsm_x4(uint32_t& r0, uint32_t& r1,
                                        uint32_t& r2, uint32_t& r3, uint32_t a) {
    asm volatile("ldmatrix.sync.aligned.m8n8.x4.shared.b16 {%0,%1,%2,%3}, [%4];"
                 : "=r"(r0), "=r"(r1), "=r"(r2), "=r"(r3) : "r"(a));
}

__device__ __forceinline__ void mma16816(float* d, const uint32_t* a,
                                         const uint32_t* b) {
    asm volatile(
        "mma.sync.aligned.m16n8k16.row.col.f32.f16.f16.f32 "
        "{%0,%1,%2,%3}, {%4,%5,%6,%7}, {%8,%9}, {%0,%1,%2,%3};"
        : "+f"(d[0]), "+f"(d[1]), "+f"(d[2]), "+f"(d[3])
        : "r"(a[0]), "r"(a[1]), "r"(a[2]), "r"(a[3]), "r"(b[0]), "r"(b[1]));
}

// ---------------------------------------------------------------------------
// Prep kernel (merged): blocks [0, CONVERT_BLOCKS) convert X fp32->fp16;
// blocks [CONVERT_BLOCKS, +BIN_BLOCKS) binarize+transpose W -> Wb[N,K] fp16.
// ---------------------------------------------------------------------------
__global__ void __launch_bounds__(256) prep_kernel(
    const float* __restrict__ x, const float* __restrict__ w,
    __half* __restrict__ xh, __half* __restrict__ wb) {
    int bid = blockIdx.x;
    int tid = threadIdx.x;
    if (bid < CONVERT_BLOCKS) {
        size_t i = ((size_t)bid * 256 + tid) * 8;
        float4 v0 = *reinterpret_cast<const float4*>(x + i);
        float4 v1 = *reinterpret_cast<const float4*>(x + i + 4);
        union { __half2 h[4]; uint4 u; } pk;
        pk.h[0] = __floats2half2_rn(v0.x, v0.y);
        pk.h[1] = __floats2half2_rn(v0.z, v0.w);
        pk.h[2] = __floats2half2_rn(v1.x, v1.y);
        pk.h[3] = __floats2half2_rn(v1.z, v1.w);
        *reinterpret_cast<uint4*>(xh + i) = pk.u;
    } else {
        __shared__ __half tile[32][33];
        int b = bid - CONVERT_BLOCKS;
        int n0 = (b & 63) * 32, k0 = (b >> 6) * 32;
        int tx = tid & 31, ty = tid >> 5;
#pragma unroll
        for (int r = 0; r < 32; r += 8) {
            float v = w[(size_t)(k0 + ty + r) * N_DIM + n0 + tx];
            tile[ty + r][tx] = __float2half(v < 0.0f ? 0.0f : 1.0f);
        }
        __syncthreads();
#pragma unroll
        for (int r = 0; r < 32; r += 8) {
            wb[(size_t)(n0 + ty + r) * K_DIM + k0 + tx] = tile[tx][ty + r];
        }
    }
}

// ---------------------------------------------------------------------------
// GEMM: 128x128 block tile, BK=32, 4-stage cp.async, ONE sync per iter,
// 2 CTAs/SM. 256 threads = 8 warps (2 M x 4 N), 64x32 warp tiles.
// Smem rows 64 B; swizzle: 16B-chunk ^= (row>>1)&3 (conflict-free ldsm).
// ---------------------------------------------------------------------------
__global__ void __launch_bounds__(256, 2)
bingemm_kernel(const __half* __restrict__ Xh, const __half* __restrict__ Wb,
               float* __restrict__ out) {
    extern __shared__ char smem[];
    const uint32_t sb = smem_u32(smem);

    const int tid = threadIdx.x;
    const int lane = tid & 31;
    const int wid = tid >> 5;
    const int wm = (wid >> 2) * 64;   // warp M offset (2 rows of warps)
    const int wn = (wid & 3) * 32;    // warp N offset (4 cols of warps)

    const int mBase = blockIdx.y * BM;
    const int nBase = blockIdx.x * BN;

    // ---- cp.async precompute: 4 loads/thread/iter ----------------------
    const int row0 = tid >> 2;              // 0..63
    const int chunk = tid & 3;
    const uint32_t sw0 = (uint32_t)(chunk ^ ((row0 >> 1) & 3)) * 16;
    const uint32_t sw1 = (uint32_t)(chunk ^ (((row0 + 64) >> 1) & 3)) * 16;
    const __half* gA0 = Xh + (size_t)(mBase + row0) * K_DIM + chunk * 8;
    const __half* gA1 = gA0 + (size_t)64 * K_DIM;
    const __half* gB0 = Wb + (size_t)(nBase + row0) * K_DIM + chunk * 8;
    const __half* gB1 = gB0 + (size_t)64 * K_DIM;
    const uint32_t dA0 = row0 * 64 + sw0;
    const uint32_t dA1 = (row0 + 64) * 64 + sw1;
    const uint32_t dB0 = A_STAGE_BYTES + row0 * 64 + sw0;
    const uint32_t dB1 = A_STAGE_BYTES + (row0 + 64) * 64 + sw1;

    // ---- ldmatrix addresses (stage-relative) ---------------------------
    uint32_t aAddr[4];
#pragma unroll
    for (int mi = 0; mi < 4; ++mi) {
        int r = wm + mi * 16 + (lane & 15);
        int kc = lane >> 4;
        aAddr[mi] = (uint32_t)(r * 64 + ((kc ^ ((r >> 1) & 3)) * 16));
    }
    uint32_t bAddr[2];
#pragma unroll
    for (int j = 0; j < 2; ++j) {
        int r = wn + j * 16 + (lane & 7) + ((lane >> 4) & 1) * 8;
        int kc = (lane >> 3) & 1;
        bAddr[j] = (uint32_t)(A_STAGE_BYTES + r * 64 + ((kc ^ ((r >> 1) & 3)) * 16));
    }

    float acc[4][4][4];
#pragma unroll
    for (int mi = 0; mi < 4; ++mi)
#pragma unroll
        for (int ni = 0; ni < 4; ++ni)
#pragma unroll
            for (int e = 0; e < 4; ++e) acc[mi][ni][e] = 0.0f;

    // ---- prologue: fill STAGES-1 stages --------------------------------
#pragma unroll
    for (int s = 0; s < STAGES - 1; ++s) {
        uint32_t st = sb + s * STAGE_BYTES;
        int kOff = s * BK;
        cp_async16(st + dA0, gA0 + kOff);
        cp_async16(st + dA1, gA1 + kOff);
        cp_async16(st + dB0, gB0 + kOff);
        cp_async16(st + dB1, gB1 + kOff);
        cp_commit();
    }

    // ---- mainloop: ONE __syncthreads per iteration ---------------------
    for (int it = 0; it < KTILES; ++it) {
        cp_wait<STAGES - 2>();   // stage `it` complete
        __syncthreads();         // also: everyone done reading stage it-1

        int pf = it + STAGES - 1;
        if (pf < KTILES) {       // prefetch into slot freed by stage it-1
            uint32_t st = sb + (pf & (STAGES - 1)) * STAGE_BYTES;
            int kOff = pf * BK;
            cp_async16(st + dA0, gA0 + kOff);
            cp_async16(st + dA1, gA1 + kOff);
            cp_async16(st + dB0, gB0 + kOff);
            cp_async16(st + dB1, gB1 + kOff);
        }
        cp_commit();

        uint32_t stage = sb + (it & (STAGES - 1)) * STAGE_BYTES;
#pragma unroll
        for (int s = 0; s < 2; ++s) {       // two k16 steps per BK=32
            const uint32_t kx = s * 32;     // K+16 toggle = byte 32 XOR
            uint32_t a[4][4];
#pragma unroll
            for (int mi = 0; mi < 4; ++mi)
                ldsm_x4(a[mi][0], a[mi][1], a[mi][2], a[mi][3],
                        stage + (aAddr[mi] ^ kx));
            uint32_t b[2][4];
#pragma unroll
            for (int j = 0; j < 2; ++j)
                ldsm_x4(b[j][0], b[j][1], b[j][2], b[j][3],
                        stage + (bAddr[j] ^ kx));
#pragma unroll
            for (int mi = 0; mi < 4; ++mi)
#pragma unroll
                for (int ni = 0; ni < 4; ++ni)
                    mma16816(acc[mi][ni], a[mi], &b[ni >> 1][(ni & 1) * 2]);
        }
    }

    // ---- epilogue: direct float2 stores --------------------------------
#pragma unroll
    for (int mi = 0; mi < 4; ++mi) {
#pragma unroll
        for (int h = 0; h < 2; ++h) {
            size_t row = (size_t)(mBase + wm + mi * 16 + h * 8 + (lane >> 2));
            float* p = out + row * N_DIM + nBase + wn + (lane & 3) * 2;
#pragma unroll
            for (int ni = 0; ni < 4; ++ni) {
                float2 v = make_float2(acc[mi][ni][2 * h], acc[mi][ni][2 * h + 1]);
                *reinterpret_cast<float2*>(p + ni * 8) = v;
            }
        }
    }
}

// ---------------------------------------------------------------------------
extern "C" void kernel_launch(void* const* d_in, const int* in_sizes, int n_in,
                              void* d_out, int out_size) {
    const float* x = (const float*)d_in[0];   // [8192, 2048] fp32
    const float* w = (const float*)d_in[1];   // [2048, 2048] fp32
    float* out = (float*)d_out;               // [8192, 2048] fp32

    void *xh_ptr = nullptr, *wb_ptr = nullptr;
    cudaGetSymbolAddress(&xh_ptr, g_Xh);
    cudaGetSymbolAddress(&wb_ptr, g_Wb);

    prep_kernel<<<CONVERT_BLOCKS + BIN_BLOCKS, 256>>>(
        x, w, (__half*)xh_ptr, (__half*)wb_ptr);

    cudaFuncSetAttribute(bingemm_kernel,
                         cudaFuncAttributeMaxDynamicSharedMemorySize, SMEM_TOTAL);
    bingemm_kernel<<<dim3(N_DIM / BN, B_DIM / BM), 256, SMEM_TOTAL>>>(
        (const __half*)xh_ptr, (const __half*)wb_ptr, out);
}

// round 4
// speedup vs baseline: 1.4574x; 1.0715x over previous
#include <cuda_runtime.h>
#include <cuda_fp16.h>
#include <cstdint>

// ============================================================================
// BinaryDense: out[8192,2048] = X[8192,2048] @ (W >= 0 ? 1 : 0)[2048,2048]
// Plain sm_100 target (no tcgen05). fp16 mma.sync HMMA GEMM, fp32 accum.
// R4: BK=64 (half the syncs), STAGES=3, SW128 swizzle, 2 CTAs/SM.
// ============================================================================

#define B_DIM 8192
#define K_DIM 2048
#define N_DIM 2048

#define BM 128
#define BN 128
#define BK 64
#define STAGES 3
#define KTILES (K_DIM / BK)          // 32

#define A_STAGE_BYTES (BM * BK * 2)  // 16384
#define B_STAGE_BYTES (BN * BK * 2)  // 16384
#define STAGE_BYTES (A_STAGE_BYTES + B_STAGE_BYTES)  // 32768
#define SMEM_TOTAL (STAGES * STAGE_BYTES)            // 98304 (x2 CTA = 192K)

#define CONVERT_BLOCKS 8192          // X: 8192*2048 / (256*8)
#define BIN_BLOCKS (64 * 64)         // W 32x32 tiles

// Scratch: fp16 X and binarized+transposed W (Wb is [N, K], K contiguous)
__device__ __align__(1024) __half g_Xh[(size_t)B_DIM * K_DIM];
__device__ __align__(1024) __half g_Wb[(size_t)N_DIM * K_DIM];

// ---------------------------------------------------------------------------
__device__ __forceinline__ uint32_t smem_u32(const void* p) {
    uint32_t a;
    asm("{ .reg .u64 t; cvta.to.shared.u64 t, %1; cvt.u32.u64 %0, t; }"
        : "=r"(a) : "l"(p));
    return a;
}

__device__ __forceinline__ void cp_async16(uint32_t dst, const void* src) {
    asm volatile("cp.async.cg.shared.global [%0], [%1], 16;"
                 :: "r"(dst), "l"(src) : "memory");
}
__device__ __forceinline__ void cp_commit() {
    asm volatile("cp.async.commit_group;" ::: "memory");
}
template <int N>
__device__ __forceinline__ void cp_wait() {
    asm volatile("cp.async.wait_group %0;" :: "n"(N) : "memory");
}

__device__ __forceinline__ void ldsm_x4(uint32_t& r0, uint32_t& r1,
                                        uint32_t& r2, uint32_t& r3, uint32_t a) {
    asm volatile("ldmatrix.sync.aligned.m8n8.x4.shared.b16 {%0,%1,%2,%3}, [%4];"
                 : "=r"(r0), "=r"(r1), "=r"(r2), "=r"(r3) : "r"(a));
}

__device__ __forceinline__ void mma16816(float* d, const uint32_t* a,
                                         const uint32_t* b) {
    asm volatile(
        "mma.sync.aligned.m16n8k16.row.col.f32.f16.f16.f32 "
        "{%0,%1,%2,%3}, {%4,%5,%6,%7}, {%8,%9}, {%0,%1,%2,%3};"
        : "+f"(d[0]), "+f"(d[1]), "+f"(d[2]), "+f"(d[3])
        : "r"(a[0]), "r"(a[1]), "r"(a[2]), "r"(a[3]), "r"(b[0]), "r"(b[1]));
}

// ---------------------------------------------------------------------------
// Prep kernel (merged): blocks [0, CONVERT_BLOCKS) convert X fp32->fp16;
// blocks [CONVERT_BLOCKS, +BIN_BLOCKS) binarize+transpose W -> Wb[N,K] fp16.
// ---------------------------------------------------------------------------
__global__ void __launch_bounds__(256) prep_kernel(
    const float* __restrict__ x, const float* __restrict__ w,
    __half* __restrict__ xh, __half* __restrict__ wb) {
    int bid = blockIdx.x;
    int tid = threadIdx.x;
    if (bid < CONVERT_BLOCKS) {
        size_t i = ((size_t)bid * 256 + tid) * 8;
        float4 v0 = *reinterpret_cast<const float4*>(x + i);
        float4 v1 = *reinterpret_cast<const float4*>(x + i + 4);
        union { __half2 h[4]; uint4 u; } pk;
        pk.h[0] = __floats2half2_rn(v0.x, v0.y);
        pk.h[1] = __floats2half2_rn(v0.z, v0.w);
        pk.h[2] = __floats2half2_rn(v1.x, v1.y);
        pk.h[3] = __floats2half2_rn(v1.z, v1.w);
        *reinterpret_cast<uint4*>(xh + i) = pk.u;
    } else {
        __shared__ __half tile[32][33];
        int b = bid - CONVERT_BLOCKS;
        int n0 = (b & 63) * 32, k0 = (b >> 6) * 32;
        int tx = tid & 31, ty = tid >> 5;
#pragma unroll
        for (int r = 0; r < 32; r += 8) {
            float v = w[(size_t)(k0 + ty + r) * N_DIM + n0 + tx];
            tile[ty + r][tx] = __float2half(v < 0.0f ? 0.0f : 1.0f);
        }
        __syncthreads();
#pragma unroll
        for (int r = 0; r < 32; r += 8) {
            wb[(size_t)(n0 + ty + r) * K_DIM + k0 + tx] = tile[tx][ty + r];
        }
    }
}

// ---------------------------------------------------------------------------
// GEMM: 128x128 block tile, BK=64, 3-stage cp.async, ONE sync per iter (32),
// 2 CTAs/SM. 256 threads = 8 warps (2 M x 4 N), 64x32 warp tiles.
// Smem rows 128 B (64 halfs); SW128 swizzle: 16B-chunk ^= (row & 7).
// ---------------------------------------------------------------------------
__global__ void __launch_bounds__(256, 2)
bingemm_kernel(const __half* __restrict__ Xh, const __half* __restrict__ Wb,
               float* __restrict__ out) {
    extern __shared__ char smem[];
    const uint32_t sb = smem_u32(smem);

    const int tid = threadIdx.x;
    const int lane = tid & 31;
    const int wid = tid >> 5;
    const int wm = (wid >> 2) * 64;   // warp M offset (2 rows of warps)
    const int wn = (wid & 3) * 32;    // warp N offset (4 cols of warps)

    const int mBase = blockIdx.y * BM;
    const int nBase = blockIdx.x * BN;

    // ---- cp.async precompute: 8 loads/thread/iter (4 A + 4 B) ----------
    // Tile rows are 128 B (8 x 16B chunks). Thread -> (row tid>>3 + 32p, chunk tid&7).
    const int row0 = tid >> 3;              // 0..31
    const int chunk = tid & 7;
    uint32_t dstA[4], dstB[4];
    const __half* srcA[4];
    const __half* srcB[4];
#pragma unroll
    for (int p = 0; p < 4; ++p) {
        int r = row0 + 32 * p;
        uint32_t sw = (uint32_t)(chunk ^ (r & 7)) * 16;
        dstA[p] = r * 128 + sw;
        dstB[p] = A_STAGE_BYTES + r * 128 + sw;
        srcA[p] = Xh + (size_t)(mBase + r) * K_DIM + chunk * 8;
        srcB[p] = Wb + (size_t)(nBase + r) * K_DIM + chunk * 8;
    }

    // ---- ldmatrix addresses (stage-relative; k16 step s => XOR s<<5) ---
    uint32_t aAddr[4];
#pragma unroll
    for (int mi = 0; mi < 4; ++mi) {
        int r = wm + mi * 16 + (lane & 15);
        int kc0 = lane >> 4;
        aAddr[mi] = (uint32_t)(r * 128 + ((kc0 ^ (r & 7)) * 16));
    }
    uint32_t bAddr[2];
#pragma unroll
    for (int j = 0; j < 2; ++j) {
        int r = wn + j * 16 + (lane & 7) + ((lane >> 4) & 1) * 8;
        int kc0 = (lane >> 3) & 1;
        bAddr[j] = (uint32_t)(A_STAGE_BYTES + r * 128 + ((kc0 ^ (r & 7)) * 16));
    }

    float acc[4][4][4];
#pragma unroll
    for (int mi = 0; mi < 4; ++mi)
#pragma unroll
        for (int ni = 0; ni < 4; ++ni)
#pragma unroll
            for (int e = 0; e < 4; ++e) acc[mi][ni][e] = 0.0f;

    // ---- prologue: fill STAGES-1 = 2 stages ----------------------------
#pragma unroll
    for (int s = 0; s < STAGES - 1; ++s) {
        uint32_t st = sb + s * STAGE_BYTES;
        int kOff = s * BK;
#pragma unroll
        for (int p = 0; p < 4; ++p) {
            cp_async16(st + dstA[p], srcA[p] + kOff);
            cp_async16(st + dstB[p], srcB[p] + kOff);
        }
        cp_commit();
    }

    // ---- mainloop: ONE __syncthreads per BK=64 iteration ---------------
    int ldSlot = 0, pfSlot = STAGES - 1;
    for (int it = 0; it < KTILES; ++it) {
        cp_wait<STAGES - 2>();   // stage `it` resident
        __syncthreads();         // all warps done reading stage it-1

        int pf = it + STAGES - 1;
        if (pf < KTILES) {       // prefetch into the slot freed by it-1
            uint32_t st = sb + pfSlot * STAGE_BYTES;
            int kOff = pf * BK;
#pragma unroll
            for (int p = 0; p < 4; ++p) {
                cp_async16(st + dstA[p], srcA[p] + kOff);
                cp_async16(st + dstB[p], srcB[p] + kOff);
            }
        }
        cp_commit();

        uint32_t stage = sb + ldSlot * STAGE_BYTES;
#pragma unroll
        for (int s = 0; s < 4; ++s) {       // four k16 steps per BK=64
            const uint32_t kx = (uint32_t)s << 5;   // XOR: chunk bits 1-2
            uint32_t a[4][4];
#pragma unroll
            for (int mi = 0; mi < 4; ++mi)
                ldsm_x4(a[mi][0], a[mi][1], a[mi][2], a[mi][3],
                        stage + (aAddr[mi] ^ kx));
            uint32_t b[2][4];
#pragma unroll
            for (int j = 0; j < 2; ++j)
                ldsm_x4(b[j][0], b[j][1], b[j][2], b[j][3],
                        stage + (bAddr[j] ^ kx));
#pragma unroll
            for (int mi = 0; mi < 4; ++mi)
#pragma unroll
                for (int ni = 0; ni < 4; ++ni)
                    mma16816(acc[mi][ni], a[mi], &b[ni >> 1][(ni & 1) * 2]);
        }

        if (++ldSlot == STAGES) ldSlot = 0;
        if (++pfSlot == STAGES) pfSlot = 0;
    }

    // ---- epilogue: direct float2 stores --------------------------------
#pragma unroll
    for (int mi = 0; mi < 4; ++mi) {
#pragma unroll
        for (int h = 0; h < 2; ++h) {
            size_t row = (size_t)(mBase + wm + mi * 16 + h * 8 + (lane >> 2));
            float* p = out + row * N_DIM + nBase + wn + (lane & 3) * 2;
#pragma unroll
            for (int ni = 0; ni < 4; ++ni) {
                float2 v = make_float2(acc[mi][ni][2 * h], acc[mi][ni][2 * h + 1]);
                *reinterpret_cast<float2*>(p + ni * 8) = v;
            }
        }
    }
}

// ---------------------------------------------------------------------------
extern "C" void kernel_launch(void* const* d_in, const int* in_sizes, int n_in,
                              void* d_out, int out_size) {
    const float* x = (const float*)d_in[0];   // [8192, 2048] fp32
    const float* w = (const float*)d_in[1];   // [2048, 2048] fp32
    float* out = (float*)d_out;               // [8192, 2048] fp32

    void *xh_ptr = nullptr, *wb_ptr = nullptr;
    cudaGetSymbolAddress(&xh_ptr, g_Xh);
    cudaGetSymbolAddress(&wb_ptr, g_Wb);

    prep_kernel<<<CONVERT_BLOCKS + BIN_BLOCKS, 256>>>(
        x, w, (__half*)xh_ptr, (__half*)wb_ptr);

    cudaFuncSetAttribute(bingemm_kernel,
                         cudaFuncAttributeMaxDynamicSharedMemorySize, SMEM_TOTAL);
    bingemm_kernel<<<dim3(N_DIM / BN, B_DIM / BM), 256, SMEM_TOTAL>>>(
        (const __half*)xh_ptr, (const __half*)wb_ptr, out);
}